// round 7
// baseline (speedup 1.0000x reference)
#include <cuda_runtime.h>
#include <math.h>
#include <cstdint>

typedef unsigned long long u64;

// ---------------------------------------------------------------------------
// Problem constants
// ---------------------------------------------------------------------------
#define BATCH   4
#define TSEQ    2048
#define CEMB    1024
#define NHEAD   16
#define HDIM    64
#define C3      (3*CEMB)      // 3072
#define CFF     (4*CEMB)      // 4096
#define NROWS   (BATCH*TSEQ)  // 8192
#define LN_EPS  1e-5f

// ---------------------------------------------------------------------------
// Scratch (__device__ globals; alloc-free rule)
// ---------------------------------------------------------------------------
__device__ float g_qkv[(size_t)NROWS * C3];
__device__ float g_att[(size_t)NROWS * CEMB];
__device__ float g_xn [(size_t)NROWS * CEMB];
__device__ float g_h  [(size_t)NROWS * CFF];
__device__ float g_mlp[(size_t)NROWS * CEMB];
__device__ float g_wTq[(size_t)C3  * CEMB];   // [3072,1024] K-major
__device__ float g_wT1[(size_t)CFF * CEMB];
__device__ float g_wT2[(size_t)CEMB * CFF];

// ---------------------------------------------------------------------------
// Helpers
// ---------------------------------------------------------------------------
__device__ __forceinline__ uint32_t smem_u32(const void* p) {
    uint32_t a;
    asm("{ .reg .u64 t; cvta.to.shared.u64 t, %1; cvt.u32.u64 %0, t; }"
        : "=r"(a) : "l"(p));
    return a;
}

// SW128 swizzle on byte offsets (rows are 128 bytes)
#define SWZ(o) ((o) ^ (((o) >> 3) & 0x70))

// packed fp32x2 ops (Blackwell FFMA2)
__device__ __forceinline__ u64 ffma2(u64 a, u64 b, u64 c) {
    u64 d;
    asm("fma.rn.f32x2 %0, %1, %2, %3;" : "=l"(d) : "l"(a), "l"(b), "l"(c));
    return d;
}
__device__ __forceinline__ u64 fmul2(u64 a, u64 b) {
    u64 d;
    asm("mul.rn.f32x2 %0, %1, %2;" : "=l"(d) : "l"(a), "l"(b));
    return d;
}
__device__ __forceinline__ u64 pack2(float x) {
    u64 d;
    asm("mov.b64 %0, {%1, %1};" : "=l"(d) : "r"(__float_as_uint(x)));
    return d;
}
__device__ __forceinline__ float f2lo(u64 v) { return __uint_as_float((uint32_t)v); }
__device__ __forceinline__ float f2hi(u64 v) { return __uint_as_float((uint32_t)(v >> 32)); }

__device__ __forceinline__ void cpasync16(uint32_t s, const void* g) {
    asm volatile("cp.async.cg.shared.global [%0], [%1], 16;" :: "r"(s), "l"(g));
}
__device__ __forceinline__ void cpasync_commit() {
    asm volatile("cp.async.commit_group;" ::: "memory");
}
template<int N>
__device__ __forceinline__ void cpasync_wait() {
    asm volatile("cp.async.wait_group %0;" :: "n"(N) : "memory");
}

// ---------------------------------------------------------------------------
// FFMA2 GEMM: C[M,N] = A[M,K] @ Bt[N,K]^T + bias (opt GeLU), all fp32.
// CTA tile 128x128, BK=32 floats (128B rows, SW128), 512 threads.
// Thread tile 8 rows x 4 cols; packed lanes pair over K (acc = even/odd-k
// partials, reduced lo+hi at the end). 3-stage cp.async pipeline.
// ---------------------------------------------------------------------------
#define GBK 32
#define GT_TILE 16384          // 128 rows x 128 bytes
#define GT_STAGE 32768         // A tile + B tile
#define GT_NSTAGE 3
#define GT_SMEM (GT_NSTAGE * GT_STAGE)   // 98304

template<bool GELU>
__global__ __launch_bounds__(512, 1)
void f2gemm_kernel(const float* __restrict__ A, const float* __restrict__ Bt,
                   const float* __restrict__ bias, float* __restrict__ C,
                   int M, int N, int K)
{
    extern __shared__ char sm[];
    const uint32_t sbase = smem_u32(sm);

    const int t    = threadIdx.x;
    const int lane = t & 31;
    const int rg   = t >> 5;          // warp id = row group (0..15)
    const int row0 = blockIdx.y * 128;
    const int col0 = blockIdx.x * 128;
    const int KT   = K / GBK;

    // staging coords: 1024 16B-chunks per tile, 2 per thread per operand
    const int sr0 = t >> 3;           // rows 0..63
    const int sr1 = sr0 + 64;         // rows 64..127
    const int sch = t & 7;
    const uint32_t so0 = SWZ((uint32_t)(sr0 * 128 + sch * 16));
    const uint32_t so1 = SWZ((uint32_t)(sr1 * 128 + sch * 16));

    #define G_ISSUE(kt, st)                                                    \
        {                                                                      \
            const int kk_ = (kt) * GBK;                                        \
            const uint32_t ab = sbase + (uint32_t)(st) * GT_STAGE;             \
            const uint32_t bb = ab + GT_TILE;                                  \
            cpasync16(ab + so0, A  + (size_t)(row0 + sr0) * K + kk_ + sch*4);  \
            cpasync16(ab + so1, A  + (size_t)(row0 + sr1) * K + kk_ + sch*4);  \
            cpasync16(bb + so0, Bt + (size_t)(col0 + sr0) * K + kk_ + sch*4);  \
            cpasync16(bb + so1, Bt + (size_t)(col0 + sr1) * K + kk_ + sch*4);  \
        }

    u64 acc[8][4];
    #pragma unroll
    for (int i = 0; i < 8; i++)
        #pragma unroll
        for (int j = 0; j < 4; j++)
            acc[i][j] = 0ull;

    // B row swizzle constants (runtime per lane)
    const uint32_t xb = (uint32_t)((lane & 7) << 4);

    G_ISSUE(0, 0); cpasync_commit();
    G_ISSUE(1, 1); cpasync_commit();

    int st = 0;
    for (int kt = 0; kt < KT; kt++) {
        cpasync_wait<1>();
        __syncthreads();

        const char* sa = sm + (size_t)st * GT_STAGE;
        const char* sb = sa + GT_TILE;
        // A base: rows rg*8+i ; swizzle XOR for row rg*8+i is (i&7)<<4 = i*16
        const char* abase = sa + rg * 1024;          // 8 rows * 128B
        // B bases: rows lane + 32*j
        const char* bbase0 = sb + (size_t)(lane      ) * 128;
        const char* bbase1 = sb + (size_t)(lane + 32 ) * 128;
        const char* bbase2 = sb + (size_t)(lane + 64 ) * 128;
        const char* bbase3 = sb + (size_t)(lane + 96 ) * 128;

        #pragma unroll
        for (int k2 = 0; k2 < 16; k2++) {            // k-pairs
            const uint32_t kb = (uint32_t)(8 * k2) ^ xb;
            u64 b2[4];
            b2[0] = *(const u64*)(bbase0 + kb);
            b2[1] = *(const u64*)(bbase1 + kb);
            b2[2] = *(const u64*)(bbase2 + kb);
            b2[3] = *(const u64*)(bbase3 + kb);
            u64 a2[8];
            #pragma unroll
            for (int i = 0; i < 8; i++)
                a2[i] = *(const u64*)(abase + i * 128 + ((8 * k2) ^ (i << 4)));
            #pragma unroll
            for (int i = 0; i < 8; i++)
                #pragma unroll
                for (int j = 0; j < 4; j++)
                    acc[i][j] = ffma2(a2[i], b2[j], acc[i][j]);
        }

        const int nst = (st + 2 >= GT_NSTAGE) ? st + 2 - GT_NSTAGE : st + 2;
        if (kt + 2 < KT) G_ISSUE(kt + 2, nst);
        cpasync_commit();
        st = (st + 1 == GT_NSTAGE) ? 0 : st + 1;
    }

    // epilogue: value = lo + hi (even-k + odd-k partials) + bias
    #pragma unroll
    for (int j = 0; j < 4; j++) {
        const int col = col0 + lane + 32 * j;
        const float bj = bias[col];
        #pragma unroll
        for (int i = 0; i < 8; i++) {
            const int row = row0 + rg * 8 + i;
            float v = f2lo(acc[i][j]) + f2hi(acc[i][j]) + bj;
            if (GELU) v = 0.5f * v * (1.f + erff(v * 0.70710678118654752f));
            C[(size_t)row * N + col] = v;
        }
    }
    #undef G_ISSUE
}

// ---------------------------------------------------------------------------
// Weight transpose: out[N,K] = in[K,N] (fp32)
// ---------------------------------------------------------------------------
__global__ __launch_bounds__(256)
void transpose_kernel(const float* __restrict__ in, float* __restrict__ out,
                      int R, int Ccols)
{
    __shared__ float tile[32][33];
    const int c = blockIdx.x * 32 + threadIdx.x;
    const int r = blockIdx.y * 32 + threadIdx.y;
    #pragma unroll
    for (int i = 0; i < 32; i += 8)
        tile[threadIdx.y + i][threadIdx.x] = in[(size_t)(r + i) * Ccols + c];
    __syncthreads();
    const int oc   = blockIdx.y * 32 + threadIdx.x;
    const int orow = blockIdx.x * 32 + threadIdx.y;
    #pragma unroll
    for (int i = 0; i < 32; i += 8)
        out[(size_t)(orow + i) * R + oc] = tile[threadIdx.x][threadIdx.y + i];
}

// ---------------------------------------------------------------------------
// Flash attention (causal), fp32 with f32x2 inner loops
// ---------------------------------------------------------------------------
#define ATT_P 68
#define ATT_SMEM (4 * 64 * ATT_P * 4)

__global__ __launch_bounds__(256)
void flash_attn_kernel(const float* __restrict__ qkv, float* __restrict__ y)
{
    extern __shared__ float smf[];
    float* Qs = smf;
    float* Ks = smf + 64*ATT_P;
    float* Vs = smf + 128*ATT_P;
    float* Ss = smf + 192*ATT_P;

    const int qt = blockIdx.x;
    const int bh = blockIdx.y;
    const int b  = bh >> 4;
    const int h  = bh & 15;
    const int t  = threadIdx.x;
    const int i  = t >> 2;
    const int cg = t & 3;
    const int c0 = cg << 4;
    const int qs = qt * 64;

    const size_t base = (size_t)(b * TSEQ) * C3 + h * HDIM;

    {
        const int d4 = (t & 15) * 4;
        const int r0 = t >> 4;
        #pragma unroll
        for (int rr = 0; rr < 64; rr += 16) {
            int row = r0 + rr;
            *(float4*)&Qs[row*ATT_P + d4] =
                *(const float4*)(qkv + base + (size_t)(qs + row) * C3 + d4);
        }
    }

    float m = -INFINITY, l = 0.f;
    u64 O2[8];
    #pragma unroll
    for (int c = 0; c < 8; c++) O2[c] = 0ull;

    for (int kt = 0; kt <= qt; kt++) {
        const int ks = kt * 64;
        __syncthreads();
        {
            const int d4 = (t & 15) * 4;
            const int r0 = t >> 4;
            #pragma unroll
            for (int rr = 0; rr < 64; rr += 16) {
                int row = r0 + rr;
                const float* kp = qkv + base + (size_t)(ks + row) * C3 + CEMB + d4;
                *(float4*)&Ks[row*ATT_P + d4] = *(const float4*)kp;
                *(float4*)&Vs[row*ATT_P + d4] = *(const float4*)(kp + CEMB);
            }
        }
        __syncthreads();

        // S = Q K^T with f32x2 pairs over d (even/odd partials in lo/hi)
        u64 acc2[16];
        #pragma unroll
        for (int jj = 0; jj < 16; jj++) acc2[jj] = 0ull;
        #pragma unroll 4
        for (int d4 = 0; d4 < 64; d4 += 4) {
            const u64 q01 = *(const u64*)&Qs[i*ATT_P + d4];
            const u64 q23 = *(const u64*)&Qs[i*ATT_P + d4 + 2];
            #pragma unroll
            for (int jj = 0; jj < 16; jj++) {
                const float* kr = &Ks[(c0+jj)*ATT_P + d4];
                acc2[jj] = ffma2(q01, *(const u64*)kr,       acc2[jj]);
                acc2[jj] = ffma2(q23, *(const u64*)(kr + 2), acc2[jj]);
            }
        }

        const bool diag = (kt == qt);
        float sc[16];
        float mt = -INFINITY;
        #pragma unroll
        for (int jj = 0; jj < 16; jj++) {
            float s = (f2lo(acc2[jj]) + f2hi(acc2[jj])) * 0.125f;
            if (diag && (c0 + jj) > i) s = -INFINITY;
            sc[jj] = s;
            mt = fmaxf(mt, s);
        }
        mt = fmaxf(mt, __shfl_xor_sync(0xffffffffu, mt, 1));
        mt = fmaxf(mt, __shfl_xor_sync(0xffffffffu, mt, 2));
        const float mnew = fmaxf(m, mt);

        float lt = 0.f;
        #pragma unroll
        for (int jj = 0; jj < 16; jj++) {
            float p = __expf(sc[jj] - mnew);
            Ss[i*ATT_P + c0 + jj] = p;
            lt += p;
        }
        lt += __shfl_xor_sync(0xffffffffu, lt, 1);
        lt += __shfl_xor_sync(0xffffffffu, lt, 2);

        const float scale = __expf(m - mnew);
        m = mnew;
        l = l * scale + lt;
        const u64 sc2 = pack2(scale);
        #pragma unroll
        for (int c = 0; c < 8; c++) O2[c] = fmul2(O2[c], sc2);
        __syncthreads();

        // O += P @ V (pairs over head-dim)
        for (int j = 0; j < 64; j++) {
            const u64 p2 = pack2(Ss[i*ATT_P + j]);
            const float* vrow = &Vs[j*ATT_P + c0];
            #pragma unroll
            for (int c = 0; c < 8; c++)
                O2[c] = ffma2(p2, *(const u64*)(vrow + 2*c), O2[c]);
        }
    }

    const float inv = 1.f / l;
    float* dst = y + (size_t)(b * TSEQ + qs + i) * CEMB + h * HDIM + c0;
    #pragma unroll
    for (int c = 0; c < 8; c++) {
        dst[2*c]   = f2lo(O2[c]) * inv;
        dst[2*c+1] = f2hi(O2[c]) * inv;
    }
}

// ---------------------------------------------------------------------------
// Fused residual-add + LayerNorm
// ---------------------------------------------------------------------------
__global__ __launch_bounds__(256)
void add_ln_kernel(const float* __restrict__ a, const float* __restrict__ r,
                   const float* __restrict__ gam, const float* __restrict__ bet,
                   float* __restrict__ out)
{
    const int row = blockIdx.x;
    const int t   = threadIdx.x;

    float4 va = ((const float4*)(a + (size_t)row * CEMB))[t];
    float4 vr = ((const float4*)(r + (size_t)row * CEMB))[t];
    float4 v;
    v.x = va.x + vr.x; v.y = va.y + vr.y; v.z = va.z + vr.z; v.w = va.w + vr.w;

    float s  = v.x + v.y + v.z + v.w;
    float sq = v.x*v.x + v.y*v.y + v.z*v.z + v.w*v.w;
    #pragma unroll
    for (int o = 16; o; o >>= 1) {
        s  += __shfl_xor_sync(0xffffffffu, s,  o);
        sq += __shfl_xor_sync(0xffffffffu, sq, o);
    }
    __shared__ float ps[8], pq[8];
    const int w = t >> 5, lane = t & 31;
    if (lane == 0) { ps[w] = s; pq[w] = sq; }
    __syncthreads();
    s = 0.f; sq = 0.f;
    #pragma unroll
    for (int k = 0; k < 8; k++) { s += ps[k]; sq += pq[k]; }

    const float mu   = s * (1.f / CEMB);
    const float var  = sq * (1.f / CEMB) - mu * mu;
    const float rstd = rsqrtf(var + LN_EPS);

    float4 gg = ((const float4*)gam)[t];
    float4 bb = ((const float4*)bet)[t];
    float4 o;
    o.x = (v.x - mu) * rstd * gg.x + bb.x;
    o.y = (v.y - mu) * rstd * gg.y + bb.y;
    o.z = (v.z - mu) * rstd * gg.z + bb.z;
    o.w = (v.w - mu) * rstd * gg.w + bb.w;
    ((float4*)(out + (size_t)row * CEMB))[t] = o;
}

// ---------------------------------------------------------------------------
// Launch
// ---------------------------------------------------------------------------
extern "C" void kernel_launch(void* const* d_in, const int* in_sizes, int n_in,
                              void* d_out, int out_size)
{
    const float* x     = (const float*)d_in[0];
    const float* w_qkv = (const float*)d_in[1];
    const float* b_qkv = (const float*)d_in[2];
    const float* ln1_g = (const float*)d_in[3];
    const float* ln1_b = (const float*)d_in[4];
    const float* w_fc1 = (const float*)d_in[5];
    const float* b_fc1 = (const float*)d_in[6];
    const float* w_fc2 = (const float*)d_in[7];
    const float* b_fc2 = (const float*)d_in[8];
    const float* ln2_g = (const float*)d_in[9];
    const float* ln2_b = (const float*)d_in[10];
    float* out = (float*)d_out;

    void *p_qkv, *p_att, *p_xn, *p_h, *p_mlp, *p_wq, *p_w1, *p_w2;
    cudaGetSymbolAddress(&p_qkv, g_qkv);
    cudaGetSymbolAddress(&p_att, g_att);
    cudaGetSymbolAddress(&p_xn,  g_xn);
    cudaGetSymbolAddress(&p_h,   g_h);
    cudaGetSymbolAddress(&p_mlp, g_mlp);
    cudaGetSymbolAddress(&p_wq,  g_wTq);
    cudaGetSymbolAddress(&p_w1,  g_wT1);
    cudaGetSymbolAddress(&p_w2,  g_wT2);
    float* qkv  = (float*)p_qkv;
    float* att  = (float*)p_att;
    float* xn   = (float*)p_xn;
    float* hbuf = (float*)p_h;
    float* mlp  = (float*)p_mlp;
    float* wTq  = (float*)p_wq;
    float* wT1  = (float*)p_w1;
    float* wT2  = (float*)p_w2;

    cudaFuncSetAttribute(flash_attn_kernel,
                         cudaFuncAttributeMaxDynamicSharedMemorySize, ATT_SMEM);
    cudaFuncSetAttribute((const void*)f2gemm_kernel<false>,
                         cudaFuncAttributeMaxDynamicSharedMemorySize, GT_SMEM);
    cudaFuncSetAttribute((const void*)f2gemm_kernel<true>,
                         cudaFuncAttributeMaxDynamicSharedMemorySize, GT_SMEM);

    // 0) weight transposes to [N,K] K-major
    transpose_kernel<<<dim3(C3/32,  CEMB/32), dim3(32,8)>>>(w_qkv, wTq, CEMB, C3);
    transpose_kernel<<<dim3(CFF/32, CEMB/32), dim3(32,8)>>>(w_fc1, wT1, CEMB, CFF);
    transpose_kernel<<<dim3(CEMB/32, CFF/32), dim3(32,8)>>>(w_fc2, wT2, CFF, CEMB);

    // 1) QKV projection
    f2gemm_kernel<false><<<dim3(C3/128, NROWS/128), 512, GT_SMEM>>>(
        x, wTq, b_qkv, qkv, NROWS, C3, CEMB);

    // 2) causal attention
    flash_attn_kernel<<<dim3(TSEQ/64, BATCH*NHEAD), 256, ATT_SMEM>>>(qkv, att);

    // 3) xn = LN1(x + att)
    add_ln_kernel<<<NROWS, 256>>>(x, att, ln1_g, ln1_b, xn);

    // 4) h = gelu(xn @ w_fc1 + b_fc1)
    f2gemm_kernel<true><<<dim3(CFF/128, NROWS/128), 512, GT_SMEM>>>(
        xn, wT1, b_fc1, hbuf, NROWS, CFF, CEMB);

    // 5) mlp = h @ w_fc2 + b_fc2
    f2gemm_kernel<false><<<dim3(CEMB/128, NROWS/128), 512, GT_SMEM>>>(
        hbuf, wT2, b_fc2, mlp, NROWS, CEMB, CFF);

    // 6) out = LN2(xn + mlp)
    add_ln_kernel<<<NROWS, 256>>>(xn, mlp, ln2_g, ln2_b, out);
}

// round 9
// speedup vs baseline: 1.4392x; 1.4392x over previous
#include <cuda_runtime.h>
#include <cuda_fp16.h>
#include <math.h>
#include <cstdint>

// ---------------------------------------------------------------------------
// Problem constants
// ---------------------------------------------------------------------------
#define BATCH   4
#define TSEQ    2048
#define CEMB    1024
#define NHEAD   16
#define HDIM    64
#define C3      (3*CEMB)      // 3072
#define CFF     (4*CEMB)      // 4096
#define NROWS   (BATCH*TSEQ)  // 8192
#define LN_EPS  1e-5f

// ---------------------------------------------------------------------------
// Scratch (__device__ globals; alloc-free rule)
// ---------------------------------------------------------------------------
__device__ float  g_qkv[(size_t)NROWS * C3];     // fp32 (attention input)
__device__ float  g_att[(size_t)NROWS * CEMB];
__device__ float  g_xn [(size_t)NROWS * CEMB];
__device__ float  g_mlp[(size_t)NROWS * CEMB];
__device__ __half g_xh [(size_t)NROWS * CEMB];   // x in half
__device__ __half g_xnh[(size_t)NROWS * CEMB];   // xn in half
__device__ __half g_hh [(size_t)NROWS * CFF];    // gelu(fc1) in half
__device__ __half g_wTq[(size_t)C3  * CEMB];     // [3072,1024] half (K-major)
__device__ __half g_wT1[(size_t)CFF * CEMB];
__device__ __half g_wT2[(size_t)CEMB * CFF];

// ---------------------------------------------------------------------------
// Helpers
// ---------------------------------------------------------------------------
__device__ __forceinline__ uint32_t smem_u32(const void* p) {
    uint32_t a;
    asm("{ .reg .u64 t; cvta.to.shared.u64 t, %1; cvt.u32.u64 %0, t; }"
        : "=r"(a) : "l"(p));
    return a;
}

// SW128 swizzle on byte offsets (rows are 128 bytes)
#define SWZ(o) ((o) ^ (((o) >> 3) & 0x70))

__device__ __forceinline__ void ldmx4(uint32_t* r, uint32_t addr) {
    asm volatile("ldmatrix.sync.aligned.m8n8.x4.shared.b16 {%0,%1,%2,%3}, [%4];"
                 : "=r"(r[0]), "=r"(r[1]), "=r"(r[2]), "=r"(r[3]) : "r"(addr));
}

// fp16-accumulator mma (zero C): D(4 halfs in 2 regs) = A*B
__device__ __forceinline__ void mma16816_f16(uint32_t* dd, const uint32_t* a,
                                             const uint32_t* b) {
    asm volatile(
        "mma.sync.aligned.m16n8k16.row.col.f16.f16.f16.f16 "
        "{%0,%1}, {%2,%3,%4,%5}, {%6,%7}, {%8,%9};"
        : "=r"(dd[0]), "=r"(dd[1])
        : "r"(a[0]), "r"(a[1]), "r"(a[2]), "r"(a[3]),
          "r"(b[0]), "r"(b[1]), "r"(0u), "r"(0u));
}

__device__ __forceinline__ void cpasync16(uint32_t s, const void* g) {
    asm volatile("cp.async.cg.shared.global [%0], [%1], 16;" :: "r"(s), "l"(g));
}
__device__ __forceinline__ void cpasync_commit() {
    asm volatile("cp.async.commit_group;" ::: "memory");
}
template<int N>
__device__ __forceinline__ void cpasync_wait() {
    asm volatile("cp.async.wait_group %0;" :: "n"(N) : "memory");
}

// ---------------------------------------------------------------------------
// GEMM: C[M,N] = A[M,K]@Bt[N,K]^T + bias (opt GeLU). A,Bt half, C OutT.
// fp16-accumulate mma.sync, promoted to fp32 after EVERY k16 mma (chain <= 16).
// CTA tile 128x128, BK=64 halfs (128B rows), 8 warps each 64x32.
// cp.async 3-stage pipeline (96KB smem), 2 CTAs/SM.
// ---------------------------------------------------------------------------
#define BK 64
#define TILE_BYTES 16384       // 128 rows x 128 bytes
#define STAGE_BYTES 32768      // A tile + B tile
#define NSTAGE 3
#define GT_SMEM (NSTAGE * STAGE_BYTES)   // 98304

template<bool GELU, typename OutT>
__global__ __launch_bounds__(256, 2)
void hgemm_kernel(const __half* __restrict__ A, const __half* __restrict__ Bt,
                  const float* __restrict__ bias, OutT* __restrict__ C,
                  int M, int N, int K)
{
    extern __shared__ char sm[];
    const uint32_t sbase = smem_u32(sm);

    const int t    = threadIdx.x;
    const int wid  = t >> 5;
    const int lane = t & 31;
    const int wm   = wid & 1;      // 2 warp-rows of 64
    const int wn   = wid >> 1;     // 4 warp-cols of 32
    const int row0 = blockIdx.y * 128;
    const int col0 = blockIdx.x * 128;

    const int KT = K / BK;

    // per-thread staging coords (4 chunks per operand per stage)
    const int srow[4] = { (t + 0)   >> 3, (t + 256) >> 3,
                          (t + 512) >> 3, (t + 768) >> 3 };
    const int sch = t & 7;
    const uint32_t sso[4] = {
        SWZ((uint32_t)(srow[0] * 128 + sch * 16)),
        SWZ((uint32_t)(srow[1] * 128 + sch * 16)),
        SWZ((uint32_t)(srow[2] * 128 + sch * 16)),
        SWZ((uint32_t)(srow[3] * 128 + sch * 16)) };

    #define ISSUE(kt, st)                                                      \
        {                                                                      \
            const int kk_ = (kt) * BK;                                         \
            const uint32_t ab = sbase + (uint32_t)(st) * STAGE_BYTES;          \
            const uint32_t bb = ab + TILE_BYTES;                               \
            _Pragma("unroll")                                                  \
            for (int it = 0; it < 4; it++) {                                   \
                cpasync16(ab + sso[it],                                        \
                          A  + (size_t)(row0 + srow[it]) * K + kk_ + sch * 8); \
                cpasync16(bb + sso[it],                                        \
                          Bt + (size_t)(col0 + srow[it]) * K + kk_ + sch * 8); \
            }                                                                  \
        }

    float d[4][4][4];
    #pragma unroll
    for (int mt = 0; mt < 4; mt++)
        #pragma unroll
        for (int nt = 0; nt < 4; nt++)
            #pragma unroll
            for (int rr = 0; rr < 4; rr++)
                d[mt][nt][rr] = 0.f;

    // prologue: stages 0,1
    ISSUE(0, 0); cpasync_commit();
    ISSUE(1, 1); cpasync_commit();

    int st = 0;
    for (int kt = 0; kt < KT; kt++) {
        cpasync_wait<1>();       // stage kt resident
        __syncthreads();

        const uint32_t sa = sbase + (uint32_t)st * STAGE_BYTES;
        const uint32_t sb = sa + TILE_BYTES;

        #pragma unroll
        for (int kc = 0; kc < 4; kc++) {      // 4 x k16 per stage
            uint32_t afr[4][4];
            #pragma unroll
            for (int mt = 0; mt < 4; mt++) {
                const int arow = wm * 64 + mt * 16 + (lane & 15);
                const int ach  = kc * 2 + (lane >> 4);
                ldmx4(afr[mt], sa + SWZ((uint32_t)(arow * 128 + ach * 16)));
            }
            uint32_t bfr[2][4];
            #pragma unroll
            for (int nt2 = 0; nt2 < 2; nt2++) {
                const int brow = wn * 32 + nt2 * 16 + ((lane >> 4) << 3) + (lane & 7);
                const int bch  = kc * 2 + ((lane >> 3) & 1);
                ldmx4(bfr[nt2], sb + SWZ((uint32_t)(brow * 128 + bch * 16)));
            }
            #pragma unroll
            for (int mt = 0; mt < 4; mt++)
                #pragma unroll
                for (int nt = 0; nt < 4; nt++) {
                    uint32_t dd[2];
                    mma16816_f16(dd, afr[mt], &bfr[nt >> 1][(nt & 1) * 2]);
                    // promote k16 partial to fp32 (bounds fp16 chain length)
                    const float2 lo = __half22float2(*(__half2*)&dd[0]);
                    const float2 hi = __half22float2(*(__half2*)&dd[1]);
                    d[mt][nt][0] += lo.x;
                    d[mt][nt][1] += lo.y;
                    d[mt][nt][2] += hi.x;
                    d[mt][nt][3] += hi.y;
                }
        }

        // issue stage kt+2 into the slot freed at iteration kt-1
        const int nst = (st + 2 >= NSTAGE) ? st + 2 - NSTAGE : st + 2;
        if (kt + 2 < KT) ISSUE(kt + 2, nst);
        cpasync_commit();
        st = (st + 1 == NSTAGE) ? 0 : st + 1;
    }

    // epilogue: d0=(r,c) d1=(r,c+1) d2=(r+8,c) d3=(r+8,c+1); r=lane/4, c=(lane%4)*2
    const int er = lane >> 2;
    const int ec = (lane & 3) * 2;
    #pragma unroll
    for (int mt = 0; mt < 4; mt++) {
        #pragma unroll
        for (int nt = 0; nt < 4; nt++) {
            const int col = col0 + wn * 32 + nt * 8 + ec;
            const float b0 = bias[col], b1 = bias[col + 1];
            #pragma unroll
            for (int hf = 0; hf < 2; hf++) {
                const int row = row0 + wm * 64 + mt * 16 + er + hf * 8;
                float v0 = d[mt][nt][hf * 2 + 0] + b0;
                float v1 = d[mt][nt][hf * 2 + 1] + b1;
                if (GELU) {
                    v0 = 0.5f * v0 * (1.f + erff(v0 * 0.70710678118654752f));
                    v1 = 0.5f * v1 * (1.f + erff(v1 * 0.70710678118654752f));
                }
                OutT* dst = C + (size_t)row * N + col;
                if (sizeof(OutT) == 4) {
                    *(float2*)dst = make_float2(v0, v1);
                } else {
                    *(__half2*)dst = __floats2half2_rn(v0, v1);
                }
            }
        }
    }
    #undef ISSUE
}

// ---------------------------------------------------------------------------
// fp32 -> fp16 convert
// ---------------------------------------------------------------------------
__global__ __launch_bounds__(256)
void f2h_kernel(const float* __restrict__ in, __half* __restrict__ out, int n4)
{
    const int i = blockIdx.x * 256 + threadIdx.x;
    if (i < n4) {
        float4 v = ((const float4*)in)[i];
        ((__half2*)out)[2*i]   = __floats2half2_rn(v.x, v.y);
        ((__half2*)out)[2*i+1] = __floats2half2_rn(v.z, v.w);
    }
}

// ---------------------------------------------------------------------------
// Weight transpose + convert: out_h[n][k] = (half) in[k][n]
// ---------------------------------------------------------------------------
__global__ __launch_bounds__(256)
void transpose_h_kernel(const float* __restrict__ in, __half* __restrict__ out,
                        int R, int Ccols)   // in is [R][Ccols]
{
    __shared__ float tile[32][33];
    const int c = blockIdx.x * 32 + threadIdx.x;
    const int r = blockIdx.y * 32 + threadIdx.y;
    #pragma unroll
    for (int i = 0; i < 32; i += 8)
        tile[threadIdx.y + i][threadIdx.x] = in[(size_t)(r + i) * Ccols + c];
    __syncthreads();
    const int oc   = blockIdx.y * 32 + threadIdx.x;  // out col = orig row (K)
    const int orow = blockIdx.x * 32 + threadIdx.y;  // out row = orig col (N)
    #pragma unroll
    for (int i = 0; i < 32; i += 8)
        out[(size_t)(orow + i) * R + oc] = __float2half(tile[threadIdx.x][threadIdx.y + i]);
}

// ---------------------------------------------------------------------------
// Flash attention (causal), fp32
// ---------------------------------------------------------------------------
#define ATT_P 68
#define ATT_SMEM (4 * 64 * ATT_P * 4)

__global__ __launch_bounds__(256)
void flash_attn_kernel(const float* __restrict__ qkv, float* __restrict__ y)
{
    extern __shared__ float smf[];
    float* Qs = smf;
    float* Ks = smf + 64*ATT_P;
    float* Vs = smf + 128*ATT_P;
    float* Ss = smf + 192*ATT_P;

    const int qt = blockIdx.x;
    const int bh = blockIdx.y;
    const int b  = bh >> 4;
    const int h  = bh & 15;
    const int t  = threadIdx.x;
    const int i  = t >> 2;
    const int cg = t & 3;
    const int c0 = cg << 4;
    const int qs = qt * 64;

    const size_t base = (size_t)(b * TSEQ) * C3 + h * HDIM;

    {
        const int d4 = (t & 15) * 4;
        const int r0 = t >> 4;
        #pragma unroll
        for (int rr = 0; rr < 64; rr += 16) {
            int row = r0 + rr;
            *(float4*)&Qs[row*ATT_P + d4] =
                *(const float4*)(qkv + base + (size_t)(qs + row) * C3 + d4);
        }
    }

    float m = -INFINITY, l = 0.f;
    float O[16];
    #pragma unroll
    for (int j = 0; j < 16; j++) O[j] = 0.f;

    for (int kt = 0; kt <= qt; kt++) {
        const int ks = kt * 64;
        __syncthreads();
        {
            const int d4 = (t & 15) * 4;
            const int r0 = t >> 4;
            #pragma unroll
            for (int rr = 0; rr < 64; rr += 16) {
                int row = r0 + rr;
                const float* kp = qkv + base + (size_t)(ks + row) * C3 + CEMB + d4;
                *(float4*)&Ks[row*ATT_P + d4] = *(const float4*)kp;
                *(float4*)&Vs[row*ATT_P + d4] = *(const float4*)(kp + CEMB);
            }
        }
        __syncthreads();

        float acc[16];
        #pragma unroll
        for (int jj = 0; jj < 16; jj++) acc[jj] = 0.f;
        #pragma unroll 4
        for (int d4 = 0; d4 < 64; d4 += 4) {
            float4 qv = *(const float4*)&Qs[i*ATT_P + d4];
            #pragma unroll
            for (int jj = 0; jj < 16; jj++) {
                float4 kv = *(const float4*)&Ks[(c0+jj)*ATT_P + d4];
                acc[jj] += qv.x*kv.x + qv.y*kv.y + qv.z*kv.z + qv.w*kv.w;
            }
        }

        const bool diag = (kt == qt);
        float mt = -INFINITY;
        #pragma unroll
        for (int jj = 0; jj < 16; jj++) {
            float s = acc[jj] * 0.125f;
            if (diag && (c0 + jj) > i) s = -INFINITY;
            acc[jj] = s;
            mt = fmaxf(mt, s);
        }
        mt = fmaxf(mt, __shfl_xor_sync(0xffffffffu, mt, 1));
        mt = fmaxf(mt, __shfl_xor_sync(0xffffffffu, mt, 2));
        const float mnew = fmaxf(m, mt);

        float lt = 0.f;
        #pragma unroll
        for (int jj = 0; jj < 16; jj++) {
            float p = __expf(acc[jj] - mnew);
            Ss[i*ATT_P + c0 + jj] = p;
            lt += p;
        }
        lt += __shfl_xor_sync(0xffffffffu, lt, 1);
        lt += __shfl_xor_sync(0xffffffffu, lt, 2);

        const float scale = __expf(m - mnew);
        m = mnew;
        l = l * scale + lt;
        #pragma unroll
        for (int cc = 0; cc < 16; cc++) O[cc] *= scale;
        __syncthreads();

        for (int j = 0; j < 64; j++) {
            float p = Ss[i*ATT_P + j];
            const float* vrow = &Vs[j*ATT_P + c0];
            #pragma unroll
            for (int cc4 = 0; cc4 < 16; cc4 += 4) {
                float4 vv = *(const float4*)(vrow + cc4);
                O[cc4+0] = fmaf(p, vv.x, O[cc4+0]);
                O[cc4+1] = fmaf(p, vv.y, O[cc4+1]);
                O[cc4+2] = fmaf(p, vv.z, O[cc4+2]);
                O[cc4+3] = fmaf(p, vv.w, O[cc4+3]);
            }
        }
    }

    const float inv = 1.f / l;
    float* dst = y + (size_t)(b * TSEQ + qs + i) * CEMB + h * HDIM + c0;
    #pragma unroll
    for (int cc = 0; cc < 16; cc++) dst[cc] = O[cc] * inv;
}

// ---------------------------------------------------------------------------
// Fused residual-add + LayerNorm; also writes half copy for next GEMM
// ---------------------------------------------------------------------------
__global__ __launch_bounds__(256)
void add_ln_kernel(const float* __restrict__ a, const float* __restrict__ r,
                   const float* __restrict__ gam, const float* __restrict__ bet,
                   float* __restrict__ out, __half* __restrict__ outh)
{
    const int row = blockIdx.x;
    const int t   = threadIdx.x;

    float4 va = ((const float4*)(a + (size_t)row * CEMB))[t];
    float4 vr = ((const float4*)(r + (size_t)row * CEMB))[t];
    float4 v;
    v.x = va.x + vr.x; v.y = va.y + vr.y; v.z = va.z + vr.z; v.w = va.w + vr.w;

    float s  = v.x + v.y + v.z + v.w;
    float sq = v.x*v.x + v.y*v.y + v.z*v.z + v.w*v.w;
    #pragma unroll
    for (int o = 16; o; o >>= 1) {
        s  += __shfl_xor_sync(0xffffffffu, s,  o);
        sq += __shfl_xor_sync(0xffffffffu, sq, o);
    }
    __shared__ float ps[8], pq[8];
    const int w = t >> 5, lane = t & 31;
    if (lane == 0) { ps[w] = s; pq[w] = sq; }
    __syncthreads();
    s = 0.f; sq = 0.f;
    #pragma unroll
    for (int k = 0; k < 8; k++) { s += ps[k]; sq += pq[k]; }

    const float mu   = s * (1.f / CEMB);
    const float var  = sq * (1.f / CEMB) - mu * mu;
    const float rstd = rsqrtf(var + LN_EPS);

    float4 gg = ((const float4*)gam)[t];
    float4 bb = ((const float4*)bet)[t];
    float4 o;
    o.x = (v.x - mu) * rstd * gg.x + bb.x;
    o.y = (v.y - mu) * rstd * gg.y + bb.y;
    o.z = (v.z - mu) * rstd * gg.z + bb.z;
    o.w = (v.w - mu) * rstd * gg.w + bb.w;
    ((float4*)(out + (size_t)row * CEMB))[t] = o;
    __half2* oh = (__half2*)(outh + (size_t)row * CEMB);
    oh[2*t]   = __floats2half2_rn(o.x, o.y);
    oh[2*t+1] = __floats2half2_rn(o.z, o.w);
}

// ---------------------------------------------------------------------------
// Launch
// ---------------------------------------------------------------------------
extern "C" void kernel_launch(void* const* d_in, const int* in_sizes, int n_in,
                              void* d_out, int out_size)
{
    const float* x     = (const float*)d_in[0];
    const float* w_qkv = (const float*)d_in[1];
    const float* b_qkv = (const float*)d_in[2];
    const float* ln1_g = (const float*)d_in[3];
    const float* ln1_b = (const float*)d_in[4];
    const float* w_fc1 = (const float*)d_in[5];
    const float* b_fc1 = (const float*)d_in[6];
    const float* w_fc2 = (const float*)d_in[7];
    const float* b_fc2 = (const float*)d_in[8];
    const float* ln2_g = (const float*)d_in[9];
    const float* ln2_b = (const float*)d_in[10];
    float* out = (float*)d_out;

    void *p_qkv, *p_att, *p_xn, *p_mlp, *p_xh, *p_xnh, *p_hh, *p_wq, *p_w1, *p_w2;
    cudaGetSymbolAddress(&p_qkv, g_qkv);
    cudaGetSymbolAddress(&p_att, g_att);
    cudaGetSymbolAddress(&p_xn,  g_xn);
    cudaGetSymbolAddress(&p_mlp, g_mlp);
    cudaGetSymbolAddress(&p_xh,  g_xh);
    cudaGetSymbolAddress(&p_xnh, g_xnh);
    cudaGetSymbolAddress(&p_hh,  g_hh);
    cudaGetSymbolAddress(&p_wq,  g_wTq);
    cudaGetSymbolAddress(&p_w1,  g_wT1);
    cudaGetSymbolAddress(&p_w2,  g_wT2);
    float*  qkv  = (float*)p_qkv;
    float*  att  = (float*)p_att;
    float*  xn   = (float*)p_xn;
    float*  mlp  = (float*)p_mlp;
    __half* xh   = (__half*)p_xh;
    __half* xnh  = (__half*)p_xnh;
    __half* hh   = (__half*)p_hh;
    __half* wTq  = (__half*)p_wq;
    __half* wT1  = (__half*)p_w1;
    __half* wT2  = (__half*)p_w2;

    cudaFuncSetAttribute(flash_attn_kernel,
                         cudaFuncAttributeMaxDynamicSharedMemorySize, ATT_SMEM);
    cudaFuncSetAttribute((const void*)hgemm_kernel<false, float>,
                         cudaFuncAttributeMaxDynamicSharedMemorySize, GT_SMEM);
    cudaFuncSetAttribute((const void*)hgemm_kernel<true, __half>,
                         cudaFuncAttributeMaxDynamicSharedMemorySize, GT_SMEM);

    // 0) conversions
    f2h_kernel<<<(NROWS*CEMB/4 + 255)/256, 256>>>(x, xh, NROWS*CEMB/4);
    transpose_h_kernel<<<dim3(C3/32,  CEMB/32), dim3(32,8)>>>(w_qkv, wTq, CEMB, C3);
    transpose_h_kernel<<<dim3(CFF/32, CEMB/32), dim3(32,8)>>>(w_fc1, wT1, CEMB, CFF);
    transpose_h_kernel<<<dim3(CEMB/32, CFF/32), dim3(32,8)>>>(w_fc2, wT2, CFF, CEMB);

    // 1) QKV projection (fp32 out)
    hgemm_kernel<false, float><<<dim3(C3/128, NROWS/128), 256, GT_SMEM>>>(
        xh, wTq, b_qkv, qkv, NROWS, C3, CEMB);

    // 2) causal attention (fp32)
    flash_attn_kernel<<<dim3(TSEQ/64, BATCH*NHEAD), 256, ATT_SMEM>>>(qkv, att);

    // 3) xn = LN1(x + att) (+ half copy)
    add_ln_kernel<<<NROWS, 256>>>(x, att, ln1_g, ln1_b, xn, xnh);

    // 4) h = gelu(xn @ w_fc1 + b_fc1) (half out)
    hgemm_kernel<true, __half><<<dim3(CFF/128, NROWS/128), 256, GT_SMEM>>>(
        xnh, wT1, b_fc1, hh, NROWS, CFF, CEMB);

    // 5) mlp = h @ w_fc2 + b_fc2 (fp32 out)
    hgemm_kernel<false, float><<<dim3(CEMB/128, NROWS/128), 256, GT_SMEM>>>(
        hh, wT2, b_fc2, mlp, NROWS, CEMB, CFF);

    // 6) out = LN2(xn + mlp)  (half copy to dead buffer)
    add_ln_kernel<<<NROWS, 256>>>(xn, mlp, ln2_g, ln2_b, out, xnh);
}